// round 6
// baseline (speedup 1.0000x reference)
#include <cuda_runtime.h>
#include <cstdint>

// Problem shape (fixed by reference setup_inputs)
#define Bn 4
#define Cn 32
#define Hn 480
#define Wn 854
#define HWn (Hn * Wn)          // 409920
#define CHWn (Cn * HWn)

// ---------------------------------------------------------------------------
// Channel-quad-major accumulation slab for ONE batch (52.5MB, L2-resident):
// logical layout slab[g][pix] (g = channel quad 0..7), each element = float4
// holding channels 4g..4g+3 of one pixel. Reused for b=0..3. Statically zero
// at load; drain re-zeros everything it reads, so the "slab is zero on entry
// to scatter" invariant holds for every call / graph replay.
// ---------------------------------------------------------------------------
__device__ float4 g_slab[8 * HWn];

__device__ __forceinline__ void red4(float* p, float a, float b, float c, float d) {
    asm volatile("red.global.add.v4.f32 [%0], {%1, %2, %3, %4};"
                 :: "l"(p), "f"(a), "f"(b), "f"(c), "f"(d) : "memory");
}

// ---------------------------------------------------------------------------
// Scatter (one batch): one thread per source pixel, 4 corners x 8 channel-
// groups of red.v4. im0/flow reads streaming so the slab keeps L2.
// ---------------------------------------------------------------------------
__global__ void __launch_bounds__(256) scatter_kernel(
    const float*  __restrict__ im0,
    const float2* __restrict__ flow,
    int b)
{
    const int p = blockIdx.x * blockDim.x + threadIdx.x;
    if (p >= HWn) return;

    const int y = p / Wn;
    const int x = p - y * Wn;

    const float2 f = __ldcs(flow + (size_t)b * HWn + p);
    const float tx = (float)x + f.x;
    const float ty = (float)y + f.y;
    const float x0f = floorf(tx);
    const float y0f = floorf(ty);
    const float fx = tx - x0f;
    const float fy = ty - y0f;
    const int x0 = (int)x0f;
    const int y0 = (int)y0f;

    const float gx = 1.f - fx;
    const float gy = 1.f - fy;
    const float w00 = gx * gy;
    const float w01 = fx * gy;
    const float w10 = gx * fy;
    const float w11 = fx * fy;

    const bool vx0 = (unsigned)x0 < (unsigned)Wn;
    const bool vx1 = (unsigned)(x0 + 1) < (unsigned)Wn;
    const bool vy0 = (unsigned)y0 < (unsigned)Hn;
    const bool vy1 = (unsigned)(y0 + 1) < (unsigned)Hn;
    const bool v00 = vy0 && vx0;
    const bool v01 = vy0 && vx1;
    const bool v10 = vy1 && vx0;
    const bool v11 = vy1 && vx1;

    const long long d00 = (long long)y0 * Wn + x0;   // pixel idx; deref only if valid
    const float* __restrict__ src = im0 + (size_t)b * CHWn + p;

    #pragma unroll
    for (int g = 0; g < 8; g++) {
        const float a  = __ldcs(src + (size_t)(4 * g + 0) * HWn);
        const float bv = __ldcs(src + (size_t)(4 * g + 1) * HWn);
        const float c  = __ldcs(src + (size_t)(4 * g + 2) * HWn);
        const float d  = __ldcs(src + (size_t)(4 * g + 3) * HWn);
        float* q = (float*)g_slab + ((long long)g * HWn + d00) * 4;
        if (v00) red4(q,              w00 * a, w00 * bv, w00 * c, w00 * d);
        if (v01) red4(q + 4,          w01 * a, w01 * bv, w01 * c, w01 * d);
        if (v10) red4(q + 4 * Wn,     w10 * a, w10 * bv, w10 * c, w10 * d);
        if (v11) red4(q + 4 * Wn + 4, w11 * a, w11 * bv, w11 * c, w11 * d);
    }
}

// ---------------------------------------------------------------------------
// 4x4 butterfly transpose across lane quads: on entry lane 4k+m holds the
// 4-channel float4 of pixel (pbase+4k+m); on exit lane 4k+m holds channel m
// values of pixels pbase+4k .. pbase+4k+3.
// ---------------------------------------------------------------------------
__device__ __forceinline__ void xpose4(float r[4], int lane) {
    float u = (lane & 1) ? r[0] : r[1];
    u = __shfl_xor_sync(0xffffffffu, u, 1);
    if (lane & 1) r[0] = u; else r[1] = u;
    float w = (lane & 1) ? r[2] : r[3];
    w = __shfl_xor_sync(0xffffffffu, w, 1);
    if (lane & 1) r[2] = w; else r[3] = w;
    float u2 = (lane & 2) ? r[0] : r[2];
    u2 = __shfl_xor_sync(0xffffffffu, u2, 2);
    if (lane & 2) r[0] = u2; else r[2] = u2;
    float w2 = (lane & 2) ? r[1] : r[3];
    w2 = __shfl_xor_sync(0xffffffffu, w2, 2);
    if (lane & 2) r[1] = w2; else r[3] = w2;
}

// ---------------------------------------------------------------------------
// Drain (one batch): slab[g][pix] -> NCHW out, re-zeroing the slab.
// No SMEM, no barriers. Per float4: coalesced LDG.128 + zero STG.128 +
// 4 SHFL + STG.128 to out (streaming). blockIdx.y = channel quad g.
// Tail iterations are warp-uniform (all offsets are multiples of 32).
// ---------------------------------------------------------------------------
#define DUNROLL 8

__global__ void __launch_bounds__(256) drain_kernel(float* __restrict__ out, int b)
{
    const int g = blockIdx.y;
    const int t = threadIdx.x;
    const int lane = t & 31;

    float4* slabg = g_slab + (size_t)g * HWn;
    float* outc = out + (size_t)b * CHWn + (size_t)(4 * g + (lane & 3)) * HWn;

    const int p0 = blockIdx.x * (256 * DUNROLL) + t;

    #pragma unroll
    for (int it = 0; it < DUNROLL; it++) {
        const int p = p0 + it * 256;
        if (p < HWn) {
            float4 v = slabg[p];
            slabg[p] = make_float4(0.f, 0.f, 0.f, 0.f);
            float r[4] = {v.x, v.y, v.z, v.w};
            xpose4(r, lane);
            const int pq = p & ~3;
            __stcs((float4*)(outc + pq), make_float4(r[0], r[1], r[2], r[3]));
        }
    }
}

// ---------------------------------------------------------------------------
// Harness entry: per batch, scatter into the L2-resident slab then drain it
// (shuffle-transpose + re-zero). 8 launches, graph-capturable, alloc-free.
// ---------------------------------------------------------------------------
extern "C" void kernel_launch(void* const* d_in, const int* in_sizes, int n_in,
                              void* d_out, int out_size) {
    const float*  im0  = (const float*)d_in[0];
    const float2* flow = (const float2*)d_in[1];
    float* out = (float*)d_out;

    const dim3 dgrid((HWn + 256 * DUNROLL - 1) / (256 * DUNROLL), 8, 1);
    for (int b = 0; b < Bn; b++) {
        scatter_kernel<<<(HWn + 255) / 256, 256>>>(im0, flow, b);
        drain_kernel<<<dgrid, 256>>>(out, b);
    }
}